// round 17
// baseline (speedup 1.0000x reference)
#include <cuda_runtime.h>
#include <cuda_fp16.h>
#include <cstdint>

#define B_ROWS 2048
#define CDIM   65536
#define DK     256
#define NNEG   50
#define CAP    6144
#define NTILES 512                 // 128-wide N tiles

// ---------------- device global scratch (no allocation calls) --------------
__device__ __half g_hs[(size_t)B_ROWS * CDIM];             // 256 MB fp16 scores
__device__ float g_tilemax[(size_t)B_ROWS * NTILES];       // 4 MB (lab-excluded)
__device__ float g_rowloss[B_ROWS];
__device__ int   g_lab[B_ROWS];
__device__ unsigned g_done;
__device__ __half g_ah[(size_t)B_ROWS * DK];               // A fp16
__device__ __half g_bh[(size_t)CDIM * DK];                 // B fp16 (32 MB)

// ---------------- PTX helpers (baseline ISA only) --------------------------
__device__ __forceinline__ uint32_t smem_u32(const void* p) {
    uint32_t a;
    asm("{ .reg .u64 t; cvta.to.shared.u64 t, %1; cvt.u32.u64 %0, t; }"
        : "=r"(a) : "l"(p));
    return a;
}
__device__ __forceinline__ void cpa16(uint32_t dst, const void* src) {
    asm volatile("cp.async.cg.shared.global [%0], [%1], 16;"
                 :: "r"(dst), "l"(__cvta_generic_to_global(src)));
}
#define CPA_COMMIT() asm volatile("cp.async.commit_group;" ::: "memory")
#define CPA_WAIT0()  asm volatile("cp.async.wait_group 0;" ::: "memory")
#define CPA_WAIT1()  asm volatile("cp.async.wait_group 1;" ::: "memory")

#define LDSM4(r, addr)                                                         \
    asm volatile("ldmatrix.sync.aligned.m8n8.x4.shared.b16 {%0,%1,%2,%3},[%4];"\
        : "=r"((r)[0]), "=r"((r)[1]), "=r"((r)[2]), "=r"((r)[3]) : "r"(addr))

#define MMA16816(d, a, b0, b1)                                                 \
    asm volatile("mma.sync.aligned.m16n8k16.row.col.f32.f16.f16.f32 "          \
        "{%0,%1,%2,%3},{%4,%5,%6,%7},{%8,%9},{%0,%1,%2,%3};"                   \
        : "+f"((d)[0]), "+f"((d)[1]), "+f"((d)[2]), "+f"((d)[3])               \
        : "r"((a)[0]), "r"((a)[1]), "r"((a)[2]), "r"((a)[3]),                  \
          "r"(b0), "r"(b1))

__device__ __forceinline__ uint32_t pkh(__half a, __half b) {
    __half2 p; p.x = a; p.y = b;
    return *(uint32_t*)&p;
}
__device__ __forceinline__ void stcs32(__half* p, uint32_t v) {
    __stcs((unsigned int*)p, v);
}

// ---------------- monotone fp16-bit key map ---------------------------------
__device__ __forceinline__ unsigned monoh(unsigned short h) {
    return (h & 0x8000u) ? (unsigned)(unsigned short)~h : (unsigned)(h | 0x8000u);
}
__device__ __forceinline__ float unmonoh(unsigned u) {
    unsigned short h = (u & 0x8000u) ? (unsigned short)(u & 0x7fffu)
                                     : (unsigned short)~u;
    __half v = *(__half*)&h;
    return __half2float(v);
}

// ---------------- block reductions ------------------------------------------
__device__ __forceinline__ int blockSumI(int v, int* sred, int tid) {
#pragma unroll
    for (int o = 16; o; o >>= 1) v += __shfl_xor_sync(0xffffffffu, v, o);
    if ((tid & 31) == 0) sred[tid >> 5] = v;
    __syncthreads();
    int tot = 0;
#pragma unroll
    for (int w = 0; w < 8; w++) tot += sred[w];
    __syncthreads();
    return tot;
}
__device__ __forceinline__ float blockSumF(float v, float* sred, int tid) {
#pragma unroll
    for (int o = 16; o; o >>= 1) v += __shfl_xor_sync(0xffffffffu, v, o);
    if ((tid & 31) == 0) sred[tid >> 5] = v;
    __syncthreads();
    float tot = 0.f;
#pragma unroll
    for (int w = 0; w < 8; w++) tot += sred[w];
    __syncthreads();
    return tot;
}
__device__ __forceinline__ float blockMinF(float v, float* sred, int tid) {
#pragma unroll
    for (int o = 16; o; o >>= 1) v = fminf(v, __shfl_xor_sync(0xffffffffu, v, o));
    if ((tid & 31) == 0) sred[tid >> 5] = v;
    __syncthreads();
    float tot = sred[0];
#pragma unroll
    for (int w = 1; w < 8; w++) tot = fminf(tot, sred[w]);
    __syncthreads();
    return tot;
}

// ===========================================================================
// Kernel 0: decode labels (int64 vs int32 ambiguity) + clamp + reset counter
// ===========================================================================
__global__ void k_declab(const void* __restrict__ labp) {
    __shared__ int s_nz;
    const unsigned* w = (const unsigned*)labp;
    if (threadIdx.x == 0) { s_nz = 0; g_done = 0u; }
    __syncthreads();
    int nz = 0;
    for (int i = threadIdx.x; i < B_ROWS / 2; i += 256)
        if (w[2 * i + 1] != 0u) nz = 1;
    if (nz) atomicOr(&s_nz, 1);
    __syncthreads();
    bool is64 = (s_nz == 0);
    for (int r = threadIdx.x; r < B_ROWS; r += 256) {
        long long v = is64 ? ((const long long*)labp)[r] : (long long)((const int*)labp)[r];
        if (v < 0) v = 0;
        if (v > CDIM - 1) v = CDIM - 1;
        g_lab[r] = (int)v;
    }
}

// ===========================================================================
// Kernel 0b: fused fp32 -> fp16 conversion for f (A) and centers (B)
// ===========================================================================
#define A_F4 ((B_ROWS * DK) / 4)          // 131072 float4
#define B_F4 ((CDIM * DK) / 4)            // 4194304 float4
__global__ __launch_bounds__(256) void k_conv2(const float* __restrict__ F,
                                               const float* __restrict__ C) {
    size_t i = (size_t)blockIdx.x * 256 + threadIdx.x;
    const float4* src;
    uint2* dst;
    if (i < A_F4) { src = (const float4*)F + i; dst = (uint2*)g_ah + i; }
    else          { size_t j = i - A_F4; src = (const float4*)C + j; dst = (uint2*)g_bh + j; }
    float4 v = *src;
    *dst = make_uint2(
        pkh(__float2half(v.x), __float2half(v.y)),
        pkh(__float2half(v.z), __float2half(v.w)));
}

// ===========================================================================
// Kernel 1: HMMA GEMM. CTA tile 128(M)x128(N), 8 warps 2x4 (warp 64x32),
// 256 threads, 2 CTA/SM (16 warps/SM). Pure fp16, fp32 accumulate.
// 3-stage cp.async pipeline, stage = k-chunk of 64 (128B rows), ONE
// __syncthreads per stage (4 total). Swizzle: 16B slot = piece ^ (row&7).
//   A at 0 (128 rows x 128B), B at 16384. Stage 32KB, x3 = 96KB/CTA.
// Epilogue: fp16 streaming score store + lab-excluded per-row tile max.
// ===========================================================================
__global__ __launch_bounds__(256, 2) void k_gemm_mma() {
    extern __shared__ __align__(16) char smem[];
    const uint32_t sb = smem_u32(smem);
    const int tid = threadIdx.x, lane = tid & 31, wid = tid >> 5;
    const int wm = wid & 1, wn = wid >> 1;          // warp grid 2(M) x 4(N)
    const int g = lane >> 2, tig = lane & 3;
    const int m0 = blockIdx.x * 128;
    const int n0t = blockIdx.y;                      // 128-wide N tile index

    float acc[4][4][4] = {};                         // [mi][ni][4]

    // loader: thread -> row (tid>>1, 0..127), 64B half (tid&1), 4 pieces
    const int lrow = tid >> 1, lp0 = (tid & 1) * 4;
    const uint32_t lXor = (uint32_t)(lrow & 7);

    // ldmatrix lane constants
    const int r15 = lane & 15, khalf = (lane >> 4) & 1;
    const uint32_t aBase = (uint32_t)((wm * 64 + r15) * 128);
    const uint32_t aXor = (uint32_t)(r15 & 7);
    const int rb = (lane & 7) + ((lane >> 4) & 1) * 8, kbh = (lane >> 3) & 1;
    const uint32_t bBase = (uint32_t)((wn * 32 + rb) * 128);
    const uint32_t bXor = (uint32_t)(rb & 7);

#define LOAD_STAGE(kt, bufi)                                                   \
    do {                                                                       \
        uint32_t st_ = sb + (bufi) * 32768;                                    \
        const __half* ga_ = g_ah + (size_t)(m0 + lrow) * DK + (kt) * 64;       \
        const __half* gb_ = g_bh + (size_t)(n0t * 128 + lrow) * DK + (kt) * 64;\
        uint32_t ra_ = st_ + lrow * 128;                                       \
        _Pragma("unroll")                                                      \
        for (int q_ = 0; q_ < 4; q_++) {                                       \
            int p_ = lp0 + q_;                                                 \
            uint32_t sl_ = ((uint32_t)p_ ^ lXor) << 4;                         \
            cpa16(ra_ + sl_,          ga_ + p_ * 8);                           \
            cpa16(ra_ + 16384 + sl_,  gb_ + p_ * 8);                           \
        }                                                                      \
        CPA_COMMIT();                                                          \
    } while (0)

    LOAD_STAGE(0, 0);
    LOAD_STAGE(1, 1);

#pragma unroll 1
    for (int kt = 0; kt < 4; kt++) {
        if (kt < 3) CPA_WAIT1(); else CPA_WAIT0();
        __syncthreads();
        if (kt + 2 < 4) LOAD_STAGE(kt + 2, (kt + 2) % 3);

        const uint32_t st = sb + (kt % 3) * 32768;
#pragma unroll
        for (int kk = 0; kk < 4; kk++) {
            const uint32_t ca = (uint32_t)(kk * 2 + khalf);
            const uint32_t cb = (uint32_t)(kk * 2 + kbh);
            const uint32_t aS = ((ca ^ aXor) << 4);
            const uint32_t bS = ((cb ^ bXor) << 4);
            uint32_t a[4][4], bh[4][2];
#pragma unroll
            for (int mi = 0; mi < 4; mi++)
                LDSM4(a[mi], st + aBase + mi * 2048 + aS);
#pragma unroll
            for (int p = 0; p < 2; p++) {
                uint32_t r4[4];
                LDSM4(r4, st + 16384 + bBase + p * 2048 + bS);
                bh[2 * p][0] = r4[0]; bh[2 * p][1] = r4[1];
                bh[2 * p + 1][0] = r4[2]; bh[2 * p + 1][1] = r4[3];
            }
#pragma unroll
            for (int mi = 0; mi < 4; mi++)
#pragma unroll
                for (int ni = 0; ni < 4; ni++)
                    MMA16816(acc[mi][ni], a[mi], bh[ni][0], bh[ni][1]);
        }
    }
#undef LOAD_STAGE
    __syncthreads();   // smem reuse for the reduction below

    // ---- epilogue: fp16 score store + lab-excluded row max (over the
    //      ROUNDED values, so k_topk's theta is exactly consistent) ----
    float* sf = (float*)smem;  // [4 wn][128 rows]
#pragma unroll
    for (int mi = 0; mi < 4; mi++) {
        int row0 = m0 + wm * 64 + mi * 16 + g;
        int row1 = row0 + 8;
        int lab0 = g_lab[row0], lab1 = g_lab[row1];
        float mx0 = -3.402823466e38f, mx1 = -3.402823466e38f;
#pragma unroll
        for (int ni = 0; ni < 4; ni++) {
            int col = n0t * 128 + wn * 32 + ni * 8 + tig * 2;
            __half h0 = __float2half(acc[mi][ni][0]);
            __half h1 = __float2half(acc[mi][ni][1]);
            __half h2 = __float2half(acc[mi][ni][2]);
            __half h3 = __float2half(acc[mi][ni][3]);
            stcs32(g_hs + (size_t)row0 * CDIM + col, pkh(h0, h1));
            stcs32(g_hs + (size_t)row1 * CDIM + col, pkh(h2, h3));
            float r0 = __half2float(h0), r1 = __half2float(h1);
            float r2 = __half2float(h2), r3 = __half2float(h3);
            if (col != lab0)     mx0 = fmaxf(mx0, r0);
            if (col + 1 != lab0) mx0 = fmaxf(mx0, r1);
            if (col != lab1)     mx1 = fmaxf(mx1, r2);
            if (col + 1 != lab1) mx1 = fmaxf(mx1, r3);
        }
#pragma unroll
        for (int o = 1; o <= 2; o <<= 1) {
            mx0 = fmaxf(mx0, __shfl_xor_sync(0xffffffffu, mx0, o));
            mx1 = fmaxf(mx1, __shfl_xor_sync(0xffffffffu, mx1, o));
        }
        if (tig == 0) {
            sf[wn * 128 + wm * 64 + mi * 16 + g]     = mx0;
            sf[wn * 128 + wm * 64 + mi * 16 + g + 8] = mx1;
        }
    }
    __syncthreads();
    if (tid < 128) {
        float m = fmaxf(fmaxf(sf[tid], sf[128 + tid]),
                        fmaxf(sf[256 + tid], sf[384 + tid]));
        g_tilemax[(size_t)(m0 + tid) * NTILES + n0t] = m;
    }
}

// ===========================================================================
// Kernel 2: per row -> exact top-50 negatives over the fp16 score world.
// Pass A: 512 tile maxima -> theta. Pass B: scan only hot tiles, compact
// 16-bit monotone half keys, binary search (<=16 iters). The LAST block
// (device counter) also performs the final mean reduction (fixed order,
// deterministic). One 256-thread block per row.
// ===========================================================================
__global__ __launch_bounds__(256) void k_topk(float* __restrict__ out) {
    const int row = blockIdx.x;
    const int tid = threadIdx.x;
    const __half* rp = g_hs + (size_t)row * CDIM;
    const int lab = g_lab[row];

    __shared__ float    s_max[256];
    __shared__ unsigned s_list[CAP];
    __shared__ unsigned short s_tiles[NTILES];
    __shared__ unsigned s_cnt, s_nt, s_last;
    __shared__ int      s_ired[8];
    __shared__ float    s_fred[8];

    // ---- pass A: thread max over 2 tile-maxima ----
    const float2* tm2 = (const float2*)(g_tilemax + (size_t)row * NTILES);
    float2 tv = tm2[tid];
    float lmax = fmaxf(tv.x, tv.y);
    s_max[tid] = lmax;
    __syncthreads();

    float gmax = -3.402823466e38f;
    int c = 0;
#pragma unroll 8
    for (int j = 0; j < 256; j++) {
        float m = s_max[j];
        gmax = fmaxf(gmax, m);
        c += (m > lmax);
    }
    float cand = (c < NNEG) ? lmax : 3.402823466e38f;
    float theta = blockMinF(cand, s_fred, tid);   // <= v50, count(>=theta) >= 50

    // theta is exactly a converted fp16 value -> exact 16-bit key
    __half th = __float2half(theta);
    const unsigned tkey = monoh(*(unsigned short*)&th);

    float posv = __half2float(rp[lab]);
    float M = fmaxf(gmax, posv);
    if (tid == 0) { s_cnt = 0; s_nt = 0; }
    __syncthreads();

    // ---- pass B: list hot tiles, warp-per-tile key compaction ----
    if (tv.x >= theta) { unsigned p = atomicAdd(&s_nt, 1u); s_tiles[p] = (unsigned short)(2 * tid); }
    if (tv.y >= theta) { unsigned p = atomicAdd(&s_nt, 1u); s_tiles[p] = (unsigned short)(2 * tid + 1); }
    __syncthreads();
    const int nt = (int)s_nt;
    const int lane = tid & 31, w = tid >> 5;
    for (int cb = 0; cb < nt; cb += 8) {
        int li = cb + w;
        if (li < nt) {
            int t = s_tiles[li];
            int base = t * 128 + lane * 4;                 // 4 halves per lane
            uint2 v2 = *(const uint2*)(rp + base);
            unsigned ws[2] = {v2.x, v2.y};
#pragma unroll
            for (int q = 0; q < 2; q++) {
                unsigned k0 = monoh((unsigned short)(ws[q] & 0xffffu));
                unsigned k1 = monoh((unsigned short)(ws[q] >> 16));
                int c0 = base + 2 * q, c1 = c0 + 1;
                if (k0 >= tkey && c0 != lab) { unsigned p = atomicAdd(&s_cnt, 1u); if (p < CAP) s_list[p] = k0; }
                if (k1 >= tkey && c1 != lab) { unsigned p = atomicAdd(&s_cnt, 1u); if (p < CAP) s_list[p] = k1; }
            }
        }
    }
    __syncthreads();
    unsigned cnt = s_cnt;

    float Sneg, Sexp;

    if (cnt <= CAP) {
        unsigned lo = tkey, hi = 0xffffu;          // 16-bit key space
        while (lo < hi) {
            unsigned mid = lo + (hi - lo + 1) / 2;
            int lc = 0;
            for (unsigned i = tid; i < cnt; i += 256)
                lc += (s_list[i] >= mid);
            int tot = blockSumI(lc, s_ired, tid);
            if (tot >= NNEG) lo = mid; else hi = mid - 1;
        }
        unsigned ucut = lo + 1;
        int lk1 = 0; float lS = 0.f, lE = 0.f;
        for (unsigned i = tid; i < cnt; i += 256) {
            unsigned u = s_list[i];
            if (u >= ucut) {
                float x = unmonoh(u);
                lk1++; lS += x; lE += expf(x - M);
            }
        }
        int k1 = blockSumI(lk1, s_ired, tid);
        float S1 = blockSumF(lS, s_fred, tid);
        float E1 = blockSumF(lE, s_fred, tid);
        float vstar = unmonoh(lo);
        float n2 = (float)(NNEG - k1);
        Sneg = S1 + n2 * vstar;
        Sexp = E1 + n2 * expf(vstar - M);
    } else {
        // exact fallback (massive ties): search with full-row scans
        unsigned lo = tkey, hi = 0xffffu;
        while (lo < hi) {
            unsigned mid = lo + (hi - lo + 1) / 2;
            int lc = 0;
            for (int i = tid; i < CDIM / 8; i += 256) {
                int base = i * 8;
                uint4 v4 = *(const uint4*)(rp + base);
                unsigned ws[4] = {v4.x, v4.y, v4.z, v4.w};
#pragma unroll
                for (int q = 0; q < 4; q++) {
                    unsigned k0 = monoh((unsigned short)(ws[q] & 0xffffu));
                    unsigned k1 = monoh((unsigned short)(ws[q] >> 16));
                    int c0 = base + 2 * q, c1 = c0 + 1;
                    if (c0 != lab) lc += (k0 >= mid);
                    if (c1 != lab) lc += (k1 >= mid);
                }
            }
            int tot = blockSumI(lc, s_ired, tid);
            if (tot >= NNEG) lo = mid; else hi = mid - 1;
        }
        unsigned ucut = lo + 1;
        int lk1 = 0; float lS = 0.f, lE = 0.f;
        for (int i = tid; i < CDIM / 8; i += 256) {
            int base = i * 8;
            uint4 v4 = *(const uint4*)(rp + base);
            unsigned ws[4] = {v4.x, v4.y, v4.z, v4.w};
#pragma unroll
            for (int q = 0; q < 4; q++) {
                unsigned k0 = monoh((unsigned short)(ws[q] & 0xffffu));
                unsigned k1 = monoh((unsigned short)(ws[q] >> 16));
                int c0 = base + 2 * q, c1 = c0 + 1;
                if (c0 != lab && k0 >= ucut) { float x = unmonoh(k0); lk1++; lS += x; lE += expf(x - M); }
                if (c1 != lab && k1 >= ucut) { float x = unmonoh(k1); lk1++; lS += x; lE += expf(x - M); }
            }
        }
        int k1 = blockSumI(lk1, s_ired, tid);
        float S1 = blockSumF(lS, s_fred, tid);
        float E1 = blockSumF(lE, s_fred, tid);
        float vstar = unmonoh(lo);
        float n2 = (float)(NNEG - k1);
        Sneg = S1 + n2 * vstar;
        Sexp = E1 + n2 * expf(vstar - M);
    }

    if (tid == 0) {
        float lse = M + logf(Sexp + expf(posv - M));
        // targets: t0 = 0.9 + 0.1/500 = 0.9002, tj = 0.0002 (x50), sum = 0.9102
        g_rowloss[row] = 0.9102f * lse - 0.9002f * posv - 0.0002f * Sneg;
        __threadfence();
        unsigned prev = atomicAdd(&g_done, 1u);
        s_last = (prev == (unsigned)(B_ROWS - 1)) ? 1u : 0u;
    }
    __syncthreads();

    // ---- last block: deterministic fixed-order mean reduction ----
    if (s_last) {
        __threadfence();  // acquire: make all rows' g_rowloss visible
        float a = 0.f;
        for (int i = tid; i < B_ROWS; i += 256) a += g_rowloss[i];
        float tot = blockSumF(a, s_fred, tid);
        if (tid == 0) out[0] = tot * (1.0f / (float)B_ROWS);
    }
}

// ===========================================================================
extern "C" void kernel_launch(void* const* d_in, const int* in_sizes, int n_in,
                              void* d_out, int out_size) {
    const float* f = nullptr;
    const float* cen = nullptr;
    const void* lab = nullptr;
    for (int i = 0; i < n_in; i++) {
        long long sz = in_sizes[i];
        if (sz == (long long)B_ROWS * DK) f = (const float*)d_in[i];
        else if (sz == (long long)CDIM * DK) cen = (const float*)d_in[i];
        else if (sz == (long long)B_ROWS) lab = d_in[i];
    }
    if (!f) f = (const float*)d_in[0];
    if (!cen) cen = (const float*)d_in[1];
    if (!lab) lab = d_in[2];

    const int SMEM_SZ = 3 * 32768;  // three stages of (A|B), 96KB/CTA
    static int s_attr_done = 0;
    if (!s_attr_done) {
        cudaFuncSetAttribute(k_gemm_mma,
                             cudaFuncAttributeMaxDynamicSharedMemorySize, SMEM_SZ);
        s_attr_done = 1;
    }

    k_declab<<<1, 256>>>(lab);
    k_conv2<<<(A_F4 + B_F4) / 256, 256>>>(f, cen);
    dim3 grid(16, 512);  // x = M tiles (co-resident CTAs share a B tile), y = N
    k_gemm_mma<<<grid, 256, SMEM_SZ>>>();
    k_topk<<<B_ROWS, 256>>>((float*)d_out);
}